// round 17
// baseline (speedup 1.0000x reference)
#include <cuda_runtime.h>
#include <cuda_bf16.h>
#include <cstdint>

// Perceive3D: out[b, k*16+c, z, h, w], k in {identity, d/dW, d/dH, d/dD} (Sobel-smoothed, /16),
// replicate padding. Separable: s=[1,2,1], d=[-1,0,1].
//
// R17: transaction-width probe — 4-wide voxels, LDG.128/STG.128 everywhere.
// Warp = 2 H rows via half-warps (lanes 0-15 row h, 16-31 row h+1), each lane owns
// 4 W voxels (float4). W-neighbor shuffles by +-1 lane; the half-warp boundary
// (lanes 15/16) coincides with the W=63/W=0 edges, so the replicate-padding clamp
// overrides the cross-segment shuffle value for free. Barrier-free skeleton,
// double-buffered plane prefetch, overlapped prologue, write-back stores (R16 base).

#define ZLEN 4
#define HTB  8   // H rows per block = 4 warps x 2 rows

__global__ __launch_bounds__(128, 5)
void perceive3d_kernel(const float* __restrict__ x, float* __restrict__ out) {
    const int lane = threadIdx.x;          // 0..31
    const int wrow = lane >> 4;            // 0/1: which of the warp's two H rows
    const int wIdx = lane & 15;            // 0..15 -> W quad (4*wIdx .. 4*wIdx+3)
    const int ly   = threadIdx.y;          // 0..3 warp id
    const int h    = blockIdx.x * HTB + 2 * ly + wrow;
    const int bc   = blockIdx.y;           // 0..63 = b*16+c
    const int z0   = blockIdx.z * ZLEN;
    const int b    = bc >> 4;
    const int c    = bc & 15;

    const size_t cstride = (size_t)64 * 64 * 64;
    const float* __restrict__ xin = x + (size_t)bc * cstride;
    float* __restrict__ out0 = out + ((size_t)(b * 64) + c) * cstride;

    const int hm = (h == 0)  ? 0  : h - 1;
    const int hp = (h == 63) ? 63 : h + 1;
    const int col = 4 * wIdx;
    const float* __restrict__ rm = xin + hm * 64 + col;
    const float* __restrict__ rc = xin + (size_t)h * 64 + col;
    const float* __restrict__ rp = xin + hp * 64 + col;
    const int line = h * 64 + col;

    const bool w0  = (wIdx == 0);    // W=0 edge (also half-warp lower boundary)
    const bool w15 = (wIdx == 15);   // W=63 edge (also half-warp upper boundary)

    // load the 3 H rows of plane z (z-clamped) for this thread's W quad
    auto loadPlane = [&](int z, float4* v) {
        int zz = z < 0 ? 0 : (z > 63 ? 63 : z);
        const size_t off = (size_t)zz * 4096;
        v[0] = *(const float4*)(rm + off);
        v[1] = *(const float4*)(rc + off);
        v[2] = *(const float4*)(rp + off);
    };

    // plane stats, vertical-first: sv = vm+2vc+vp, dv = vp-vm, then one horizontal pass.
    auto stats = [&](const float4* v, float4& P, float4& QW, float4& QH, float4& CC) {
        const float4 vm = v[0], vc = v[1], vp = v[2];
        float4 sv, dv;
        sv.x = vm.x + 2.f * vc.x + vp.x;  sv.y = vm.y + 2.f * vc.y + vp.y;
        sv.z = vm.z + 2.f * vc.z + vp.z;  sv.w = vm.w + 2.f * vc.w + vp.w;
        dv.x = vp.x - vm.x;  dv.y = vp.y - vm.y;
        dv.z = vp.z - vm.z;  dv.w = vp.w - vm.w;
        // cross-lane neighbors (cross-segment pollution fixed by the edge clamps)
        float svL = __shfl_up_sync(0xffffffffu,  sv.w, 1);
        float svR = __shfl_down_sync(0xffffffffu, sv.x, 1);
        float dvL = __shfl_up_sync(0xffffffffu,  dv.w, 1);
        float dvR = __shfl_down_sync(0xffffffffu, dv.x, 1);
        if (w0)  { svL = sv.x; dvL = dv.x; }   // replicate at W=0
        if (w15) { svR = sv.w; dvR = dv.w; }   // replicate at W=63
        P.x  = svL  + 2.f * sv.x + sv.y;   P.y  = sv.x + 2.f * sv.y + sv.z;
        P.z  = sv.y + 2.f * sv.z + sv.w;   P.w  = sv.z + 2.f * sv.w + svR;
        QW.x = sv.y - svL;   QW.y = sv.z - sv.x;
        QW.z = sv.w - sv.y;  QW.w = svR  - sv.z;
        QH.x = dvL  + 2.f * dv.x + dv.y;   QH.y = dv.x + 2.f * dv.y + dv.z;
        QH.z = dv.y + 2.f * dv.z + dv.w;   QH.w = dv.z + 2.f * dv.w + dvR;
        CC   = vc;
    };

    // emit all four outputs for plane z (STG.128, write-back)
    auto emit = [&](int z, const float4& Pp, const float4& Pn,
                    const float4& Xp, const float4& Xc, const float4& Xn,
                    const float4& Yp, const float4& Yc, const float4& Yn,
                    const float4& Cc) {
        float4 sx, sy, sz;
        sx.x = (Xp.x + 2.f * Xc.x + Xn.x) * 0.0625f;
        sx.y = (Xp.y + 2.f * Xc.y + Xn.y) * 0.0625f;
        sx.z = (Xp.z + 2.f * Xc.z + Xn.z) * 0.0625f;
        sx.w = (Xp.w + 2.f * Xc.w + Xn.w) * 0.0625f;
        sy.x = (Yp.x + 2.f * Yc.x + Yn.x) * 0.0625f;
        sy.y = (Yp.y + 2.f * Yc.y + Yn.y) * 0.0625f;
        sy.z = (Yp.z + 2.f * Yc.z + Yn.z) * 0.0625f;
        sy.w = (Yp.w + 2.f * Yc.w + Yn.w) * 0.0625f;
        sz.x = (Pn.x - Pp.x) * 0.0625f;
        sz.y = (Pn.y - Pp.y) * 0.0625f;
        sz.z = (Pn.z - Pp.z) * 0.0625f;
        sz.w = (Pn.w - Pp.w) * 0.0625f;
        const size_t o = (size_t)z * 4096 + line;
        *(float4*)(out0 + o)                = Cc;
        *(float4*)(out0 + o + 16 * cstride) = sx;
        *(float4*)(out0 + o + 32 * cstride) = sy;
        *(float4*)(out0 + o + 48 * cstride) = sz;
    };

    float4 A[3], B[3];                               // raw plane double buffer (3 rows)
    float4 Pp, Pc, Pn, Xp, Xc, Xn, Yp, Yc, Yn, Cc, Cn;

    // prologue, overlapped: planes z0-1 and z0 issued back-to-back, then z0+1 staged in A
    loadPlane(z0 - 1, A);
    loadPlane(z0,     B);
    stats(A, Pp, Xp, Yp, Cn);
    stats(B, Pc, Xc, Yc, Cc);
    loadPlane(z0 + 1, A);

    #pragma unroll
    for (int t = 0; t < ZLEN; t += 2) {
        // even step: prefetch z+2 into B (guarded), consume A (= plane z+1)
        if (t + 2 <= ZLEN) loadPlane(z0 + t + 2, B);
        stats(A, Pn, Xn, Yn, Cn);
        emit(z0 + t, Pp, Pn, Xp, Xc, Xn, Yp, Yc, Yn, Cc);
        Pp = Pc; Pc = Pn;  Xp = Xc; Xc = Xn;  Yp = Yc; Yc = Yn;  Cc = Cn;

        // odd step: prefetch z+3 into A (guarded), consume B (= plane z+2)
        if (t + 3 <= ZLEN) loadPlane(z0 + t + 3, A);
        stats(B, Pn, Xn, Yn, Cn);
        emit(z0 + t + 1, Pp, Pn, Xp, Xc, Xn, Yp, Yc, Yn, Cc);
        Pp = Pc; Pc = Pn;  Xp = Xc; Xc = Xn;  Yp = Yc; Yc = Yn;  Cc = Cn;
    }
}

extern "C" void kernel_launch(void* const* d_in, const int* in_sizes, int n_in,
                              void* d_out, int out_size) {
    const float* x = (const float*)d_in[0];
    // d_in[1] = kernels (4x3x3x3) — fixed separable stencils folded into the kernel.
    float* out = (float*)d_out;

    dim3 grid(64 / HTB, 64, 64 / ZLEN);  // (8 H tiles, B*C=64, 16 z chunks) = 8192 blocks
    dim3 block(32, 4);                   // 128 threads; warp = two H rows (half-warp each)
    perceive3d_kernel<<<grid, block>>>(x, out);
}